// round 16
// baseline (speedup 1.0000x reference)
#include <cuda_runtime.h>
#include <cuda_fp16.h>
#include <math.h>
#include <stdint.h>

#define S_LEN  4096
#define DMODEL 2048
#define NHEADS 16
#define HDIM   128
#define WIN    512

// ---------------------------------------------------------------------------
// Scratch (__device__ globals: allocation-free rule)
// ---------------------------------------------------------------------------
__device__ __half g_xh[S_LEN * DMODEL];
__device__ __half g_ah[S_LEN * DMODEL];
__device__ __half g_qh[S_LEN * DMODEL];
__device__ __half g_kh[S_LEN * DMODEL];
__device__ __half g_vh[S_LEN * DMODEL];
__device__ __half g_wq[DMODEL * DMODEL];
__device__ __half g_wk[DMODEL * DMODEL];
__device__ __half g_wv[DMODEL * DMODEL];
__device__ __half g_wo[DMODEL * DMODEL];
__device__ float2 g_rope[S_LEN * 64];

// ---------------------------------------------------------------------------
// PTX primitives (baseline sm_80+)
// ---------------------------------------------------------------------------
__device__ __forceinline__ uint32_t smem_to_u32(const void* p) {
    uint32_t a;
    asm("{ .reg .u64 t; cvta.to.shared.u64 t, %1; cvt.u32.u64 %0, t; }"
        : "=r"(a) : "l"(p));
    return a;
}

#define CP_ASYNC16(dst, src) \
    asm volatile("cp.async.cg.shared.global [%0], [%1], 16;" \
        :: "r"(dst), "l"(src) : "memory")
#define CP_COMMIT() asm volatile("cp.async.commit_group;" ::: "memory")
#define CP_WAIT1()  asm volatile("cp.async.wait_group 1;" ::: "memory")
#define CP_WAIT0()  asm volatile("cp.async.wait_group 0;" ::: "memory")

#define LDM_X4(r, addr) \
    asm volatile("ldmatrix.sync.aligned.m8n8.x4.shared.b16 {%0,%1,%2,%3}, [%4];" \
        : "=r"((r)[0]), "=r"((r)[1]), "=r"((r)[2]), "=r"((r)[3]) : "r"(addr))

#define LDM_X4_T(r, addr) \
    asm volatile("ldmatrix.sync.aligned.m8n8.x4.trans.shared.b16 {%0,%1,%2,%3}, [%4];" \
        : "=r"((r)[0]), "=r"((r)[1]), "=r"((r)[2]), "=r"((r)[3]) : "r"(addr))

#define MMA_F16(c, a, b0, b1) \
    asm volatile("mma.sync.aligned.m16n8k16.row.col.f32.f16.f16.f32 " \
        "{%0,%1,%2,%3}, {%4,%5,%6,%7}, {%8,%9}, {%0,%1,%2,%3};" \
        : "+f"((c)[0]), "+f"((c)[1]), "+f"((c)[2]), "+f"((c)[3]) \
        : "r"((a)[0]), "r"((a)[1]), "r"((a)[2]), "r"((a)[3]), "r"(b0), "r"(b1))

// ---------------------------------------------------------------------------
// RoPE cos/sin table
// ---------------------------------------------------------------------------
__global__ __launch_bounds__(256) void rope_build(float2* __restrict__ tab) {
    int idx = blockIdx.x * blockDim.x + threadIdx.x;
    if (idx >= S_LEN * 64) return;
    int t = idx & 63;
    int s = idx >> 6;
    float ang = (float)s * exp2f(-(float)t * 0.20762050593045702f);
    float sn, cs;
    sincosf(ang, &sn, &cs);
    tab[idx] = make_float2(cs, sn);
}

// ---------------------------------------------------------------------------
// fp32 -> fp16 single, 8 elems/thread
// ---------------------------------------------------------------------------
__global__ __launch_bounds__(256) void cvt_f16(const float* __restrict__ src,
                                               __half* __restrict__ dst, int n8) {
    int i = blockIdx.x * blockDim.x + threadIdx.x;
    if (i >= n8) return;
    const float4* s4 = (const float4*)src + 2 * (size_t)i;
    float4 a = s4[0], b = s4[1];
    float v[8] = {a.x, a.y, a.z, a.w, b.x, b.y, b.z, b.w};
    __align__(16) __half h[8];
#pragma unroll
    for (int j = 0; j < 8; j++) h[j] = __float2half_rn(v[j]);
    ((uint4*)dst)[i] = *(const uint4*)h;
}

// Four weight matrices fp32 -> fp16 in one launch
__global__ __launch_bounds__(256) void cvt_f16x4(
    const float* __restrict__ s0, const float* __restrict__ s1,
    const float* __restrict__ s2, const float* __restrict__ s3,
    __half* __restrict__ d0, __half* __restrict__ d1,
    __half* __restrict__ d2, __half* __restrict__ d3, int n8) {
    int i = blockIdx.x * blockDim.x + threadIdx.x;
    if (i >= n8) return;
    const int w = blockIdx.y;
    const float* src = (w == 0) ? s0 : (w == 1) ? s1 : (w == 2) ? s2 : s3;
    __half* dst = (w == 0) ? d0 : (w == 1) ? d1 : (w == 2) ? d2 : d3;
    const float4* s4 = (const float4*)src + 2 * (size_t)i;
    float4 a = s4[0], b = s4[1];
    float v[8] = {a.x, a.y, a.z, a.w, b.x, b.y, b.z, b.w};
    __align__(16) __half h[8];
#pragma unroll
    for (int j = 0; j < 8; j++) h[j] = __float2half_rn(v[j]);
    ((uint4*)dst)[i] = *(const uint4*)h;
}

// ---------------------------------------------------------------------------
// Shared GEMM mainloop: 512 threads, 16 warps, warp-tile 32x32, BK=64.
// (Converged at 2-CTA occupancy / 64-reg cap; crossbar-bound.)
// ---------------------------------------------------------------------------
#define GK DMODEL
#define NI (GK / 64)                 // 32 iterations
#define PAD_ROW_B 144                // 64 fp16 (128B) + 16B pad
#define TILE_B (128 * PAD_ROW_B)     // 18432
#define STAGE_B (2 * TILE_B)         // A, B = 36864
#define GEMM_SMEM (3 * STAGE_B)      // 110592

#define GEMM_MAINLOOP(AP, BP)                                                  \
    const __half* gsrc[2] = {                                                  \
        (AP) + (size_t)m0 * GK, (BP) + (size_t)n0 * GK};                       \
    int l_tile[4], l_row[4], l_c16[4];                                         \
    _Pragma("unroll")                                                          \
    for (int t = 0; t < 4; t++) {                                              \
        int linear = t * 512 + tid;      /* 2048 chunks per stage */           \
        l_tile[t] = linear >> 10;        /* 1024 chunks per tile  */           \
        int within = linear & 1023;                                            \
        l_row[t] = within >> 3;                                                \
        l_c16[t] = within & 7;                                                 \
    }                                                                          \
    _Pragma("unroll")                                                          \
    for (int s = 0; s < 2; s++) {                                              \
        const uint32_t sb = sbase + s * STAGE_B;                               \
        const int k0 = s * 64;                                                 \
        _Pragma("unroll")                                                      \
        for (int t = 0; t < 4; t++) {                                          \
            const __half* src =                                                \
                gsrc[l_tile[t]] + (size_t)l_row[t] * GK + k0 + l_c16[t] * 8;   \
            uint32_t dst = sb + l_tile[t] * TILE_B +                           \
                           l_row[t] * PAD_ROW_B + l_c16[t] * 16;               \
            CP_ASYNC16(dst, src);                                              \
        }                                                                      \
        CP_COMMIT();                                                           \
    }                                                                          \
    _Pragma("unroll")                                                          \
    for (int i = 0; i < 2; i++)                                                \
        _Pragma("unroll")                                                      \
        for (int j = 0; j < 4; j++)                                            \
            _Pragma("unroll")                                                  \
            for (int r = 0; r < 4; r++) acc[i][j][r] = 0.f;                    \
    const int lrow = lane & 15;                                                \
    const int lcol = (lane >> 4) * 16;                                         \
    for (int i = 0; i < NI; i++) {                                             \
        if (i < NI - 1) { CP_WAIT1(); } else { CP_WAIT0(); }                   \
        __syncthreads();                                                       \
        if (i + 2 < NI) {                                                      \
            const int k0n = (i + 2) * 64;                                      \
            const uint32_t sb = sbase + ((i + 2) % 3) * STAGE_B;               \
            _Pragma("unroll")                                                  \
            for (int t = 0; t < 4; t++) {                                      \
                const __half* src = gsrc[l_tile[t]] +                          \
                    (size_t)l_row[t] * GK + k0n + l_c16[t] * 8;                \
                uint32_t dst = sb + l_tile[t] * TILE_B +                       \
                               l_row[t] * PAD_ROW_B + l_c16[t] * 16;           \
                CP_ASYNC16(dst, src);                                          \
            }                                                                  \
            CP_COMMIT();                                                       \
        }                                                                      \
        const uint32_t sA = sbase + (i % 3) * STAGE_B;                         \
        _Pragma("unroll")                                                      \
        for (int ks = 0; ks < 4; ks++) {                                       \
            const uint32_t kb = ks * 32 + lcol;                                \
            uint32_t b[4][2];                                                  \
            _Pragma("unroll")                                                  \
            for (int j = 0; j < 2; j++) {                                      \
                uint32_t bd = sA + TILE_B +                                    \
                    (wn * 32 + j * 16 + lrow) * PAD_ROW_B + kb;                \
                uint32_t r[4];                                                 \
                LDM_X4(r, bd);                                                 \
                b[2 * j][0] = r[0]; b[2 * j + 1][0] = r[1];                    \
                b[2 * j][1] = r[2]; b[2 * j + 1][1] = r[3];                    \
            }                                                                  \
            _Pragma("unroll")                                                  \
            for (int mt = 0; mt < 2; mt++) {                                   \
                uint32_t ah[4];                                                \
                uint32_t ad = sA + (wm * 32 + mt * 16 + lrow) * PAD_ROW_B + kb;\
                LDM_X4(ah, ad);                                                \
                _Pragma("unroll")                                              \
                for (int nt = 0; nt < 4; nt++) {                               \
                    MMA_F16(acc[mt][nt], ah, b[nt][0], b[nt][1]);              \
                }                                                              \
            }                                                                  \
        }                                                                      \
    }

// ---------------------------------------------------------------------------
// QKV GEMM, single fp16 MMA; fused RoPE epilogue. blockIdx.z: 0=Q, 1=K, 2=V.
// ---------------------------------------------------------------------------
__global__ __launch_bounds__(512, 2) void gemm_qkv(
    const __half* __restrict__ Ah,
    const __half* __restrict__ B0, const __half* __restrict__ B1,
    const __half* __restrict__ B2,
    __half* __restrict__ qh, __half* __restrict__ kh, __half* __restrict__ vh,
    const float2* __restrict__ rope) {
    extern __shared__ char smem[];
    const uint32_t sbase = smem_to_u32(smem);
    const int tid  = threadIdx.x;
    const int wid  = tid >> 5;
    const int lane = tid & 31;
    const int wm   = wid & 3;
    const int wn   = wid >> 2;
    const int m0   = blockIdx.y * 128;
    const int n0   = blockIdx.x * 128;
    const int z    = blockIdx.z;
    const __half* B = (z == 0) ? B0 : (z == 1) ? B1 : B2;

    float acc[2][4][4];
    GEMM_MAINLOOP(Ah, B)

    __half* outp = (z == 0) ? qh : (z == 1) ? kh : vh;
#pragma unroll
    for (int mt = 0; mt < 2; mt++) {
        const int r = m0 + wm * 32 + mt * 16 + (lane >> 2);
#pragma unroll
        for (int nt = 0; nt < 4; nt++) {
            const int c = n0 + wn * 32 + nt * 8 + (lane & 3) * 2;
            const size_t o0 = (size_t)r * DMODEL + c;
            const size_t o1 = (size_t)(r + 8) * DMODEL + c;
            if (z == 2) {
                *(half2*)(outp + o0) = __floats2half2_rn(acc[mt][nt][0], acc[mt][nt][1]);
                *(half2*)(outp + o1) = __floats2half2_rn(acc[mt][nt][2], acc[mt][nt][3]);
            } else {
                const int t = (c & 127) >> 1;
                float2 cs0 = rope[r * 64 + t];
                float2 cs1 = rope[(r + 8) * 64 + t];
                float a1 = acc[mt][nt][0] * cs0.x - acc[mt][nt][1] * cs0.y;
                float a2 = acc[mt][nt][0] * cs0.y + acc[mt][nt][1] * cs0.x;
                float b1 = acc[mt][nt][2] * cs1.x - acc[mt][nt][3] * cs1.y;
                float b2 = acc[mt][nt][2] * cs1.y + acc[mt][nt][3] * cs1.x;
                *(half2*)(outp + o0) = __floats2half2_rn(a1, a2);
                *(half2*)(outp + o1) = __floats2half2_rn(b1, b2);
            }
        }
    }
}

// ---------------------------------------------------------------------------
// Output projection GEMM: single fp16 MMA, fp32 epilogue to d_out.
// ---------------------------------------------------------------------------
__global__ __launch_bounds__(512, 2) void gemm_out(
    const __half* __restrict__ Ah, const __half* __restrict__ Bw,
    float* __restrict__ C) {
    extern __shared__ char smem[];
    const uint32_t sbase = smem_to_u32(smem);
    const int tid  = threadIdx.x;
    const int wid  = tid >> 5;
    const int lane = tid & 31;
    const int wm   = wid & 3;
    const int wn   = wid >> 2;
    const int m0   = blockIdx.y * 128;
    const int n0   = blockIdx.x * 128;

    float acc[2][4][4];
    GEMM_MAINLOOP(Ah, Bw)

#pragma unroll
    for (int mt = 0; mt < 2; mt++) {
        const int r = m0 + wm * 32 + mt * 16 + (lane >> 2);
#pragma unroll
        for (int nt = 0; nt < 4; nt++) {
            const int c = n0 + wn * 32 + nt * 8 + (lane & 3) * 2;
            *(float2*)(C + (size_t)r * DMODEL + c) =
                make_float2(acc[mt][nt][0], acc[mt][nt][1]);
            *(float2*)(C + (size_t)(r + 8) * DMODEL + c) =
                make_float2(acc[mt][nt][2], acc[mt][nt][3]);
        }
    }
}

// ---------------------------------------------------------------------------
// HMMA flash attention: Q-tile 128 (256 threads, 8 warps x 16 q-rows),
// KV tiles of 64. Halves KV L2 traffic per query; warps skip tiles fully
// outside their causal window (exact: masked tiles contribute nothing).
// ---------------------------------------------------------------------------
#define AROW 272
#define QT_B (128 * AROW)             // 34816 (Q tile, 128 rows)
#define KT_B (64 * AROW)              // 17408 (K/V tiles, 64 rows)
#define ATTN_SMEM (QT_B + 2 * KT_B)   // 69632

#define MMA2S(s0r, s1r, a, kf)                                                 \
    MMA_F16(s0r, a, (kf)[0], (kf)[2]);                                         \
    MMA_F16(s1r, a, (kf)[1], (kf)[3]);

__global__ __launch_bounds__(256) void attn_mma(const __half* __restrict__ qh,
                                                const __half* __restrict__ kh,
                                                const __half* __restrict__ vh,
                                                __half* __restrict__ oh) {
    extern __shared__ char smem[];
    const uint32_t sbase = smem_to_u32(smem);
    const uint32_t sQ = sbase;
    const uint32_t sK = sbase + QT_B;
    const uint32_t sV = sbase + QT_B + KT_B;

    const int h    = blockIdx.y;
    const int q0   = blockIdx.x * 128;
    const int tid  = threadIdx.x;
    const int wid  = tid >> 5;
    const int lane = tid & 31;
    const int lrow = lane & 15;
    const int lcol = (lane >> 4) * 16;
    const float SCALE = 0.088388347648318447f;

    // Load Q tile (128 rows)
    for (int ch = tid; ch < 128 * 16; ch += 256) {
        int row = ch >> 4, c8 = ch & 15;
        size_t g = (size_t)(q0 + row) * DMODEL + h * HDIM + c8 * 8;
        *(uint4*)(smem + (row * AROW + c8 * 16)) = *(const uint4*)(qh + g);
    }

    float O[16][4];
#pragma unroll
    for (int i = 0; i < 16; i++)
#pragma unroll
        for (int r = 0; r < 4; r++) O[i][r] = 0.f;
    float m0 = -1e30f, m1 = -1e30f, l0 = 0.f, l1 = 0.f;

    const int qlo = q0 + wid * 16;       // warp's first q-row
    const int r0g = qlo + (lane >> 2);
    const int r1g = r0g + 8;
    const int cbeg = max(0, q0 - (WIN - 1)) & ~63;
    const int cend = q0 + 64;            // covers rows up to q0+127

    for (int c = cbeg; c <= cend; c += 64) {
        __syncthreads();
        for (int ch = tid; ch < 64 * 16; ch += 256) {
            int row = ch >> 4, c8 = ch & 15;
            size_t g = (size_t)(c + row) * DMODEL + h * HDIM + c8 * 8;
            *(uint4*)(smem + QT_B + (row * AROW + c8 * 16))        = *(const uint4*)(kh + g);
            *(uint4*)(smem + QT_B + KT_B + (row * AROW + c8 * 16)) = *(const uint4*)(vh + g);
        }
        __syncthreads();

        // Skip tiles fully outside this warp's causal window
        if (c > qlo + 15 || c + 63 < qlo - (WIN - 1)) continue;

        float S[8][4];
#pragma unroll
        for (int nt = 0; nt < 8; nt++)
#pragma unroll
            for (int r = 0; r < 4; r++) S[nt][r] = 0.f;

#pragma unroll
        for (int ks = 0; ks < 8; ks++) {
            const uint32_t kboff = ks * 32 + lcol;
            uint32_t aQ[4], kC[4], kN[4];
            LDM_X4(aQ, sQ + (wid * 16 + lrow) * AROW + kboff);
            LDM_X4(kC, sK + (lrow) * AROW + kboff);
            LDM_X4(kN, sK + (16 + lrow) * AROW + kboff);
            MMA2S(S[0], S[1], aQ, kC)
            LDM_X4(kC, sK + (32 + lrow) * AROW + kboff);
            MMA2S(S[2], S[3], aQ, kN)
            LDM_X4(kN, sK + (48 + lrow) * AROW + kboff);
            MMA2S(S[4], S[5], aQ, kC)
            MMA2S(S[6], S[7], aQ, kN)
        }

        const bool need_mask = (c + 63 > qlo) || (qlo + 15 - c >= WIN);
        if (need_mask) {
#pragma unroll
            for (int nt = 0; nt < 8; nt++) {
                int colb = c + nt * 8 + (lane & 3) * 2;
                if (colb > r0g     || r0g - colb >= WIN)     S[nt][0] = -1e30f;
                if (colb + 1 > r0g || r0g - colb - 1 >= WIN) S[nt][1] = -1e30f;
                if (colb > r1g     || r1g - colb >= WIN)     S[nt][2] = -1e30f;
                if (colb + 1 > r1g || r1g - colb - 1 >= WIN) S[nt][3] = -1e30f;
            }
        }

        float mx0 = -1e30f, mx1 = -1e30f;
#pragma unroll
        for (int nt = 0; nt < 8; nt++) {
            mx0 = fmaxf(mx0, fmaxf(S[nt][0], S[nt][1]));
            mx1 = fmaxf(mx1, fmaxf(S[nt][2], S[nt][3]));
        }
        mx0 = fmaxf(mx0, __shfl_xor_sync(0xffffffffu, mx0, 1));
        mx0 = fmaxf(mx0, __shfl_xor_sync(0xffffffffu, mx0, 2));
        mx1 = fmaxf(mx1, __shfl_xor_sync(0xffffffffu, mx1, 1));
        mx1 = fmaxf(mx1, __shfl_xor_sync(0xffffffffu, mx1, 2));

        float mn0 = fmaxf(m0, mx0 * SCALE);
        float mn1 = fmaxf(m1, mx1 * SCALE);
        float c0 = __expf(m0 - mn0);
        float c1 = __expf(m1 - mn1);
        l0 *= c0; l1 *= c1;
#pragma unroll
        for (int nt = 0; nt < 16; nt++) {
            O[nt][0] *= c0; O[nt][1] *= c0;
            O[nt][2] *= c1; O[nt][3] *= c1;
        }
        m0 = mn0; m1 = mn1;

        uint32_t P[8][2];
#pragma unroll
        for (int nt = 0; nt < 8; nt++) {
            float p0 = __expf(S[nt][0] * SCALE - m0);
            float p1 = __expf(S[nt][1] * SCALE - m0);
            float p2 = __expf(S[nt][2] * SCALE - m1);
            float p3 = __expf(S[nt][3] * SCALE - m1);
            l0 += p0 + p1; l1 += p2 + p3;
            __half2 h01 = __floats2half2_rn(p0, p1);
            __half2 h23 = __floats2half2_rn(p2, p3);
            P[nt][0] = *(uint32_t*)&h01;
            P[nt][1] = *(uint32_t*)&h23;
        }

#pragma unroll
        for (int u = 0; u < 4; u++) {
            uint32_t pa[4] = {P[2 * u][0], P[2 * u][1], P[2 * u + 1][0], P[2 * u + 1][1]};
            const uint32_t vb = sV + (u * 16 + lrow) * AROW + lcol;
            uint32_t vC[4], vN[4];
            LDM_X4_T(vC, vb);
            LDM_X4_T(vN, vb + 32);
            MMA_F16(O[0], pa, vC[0], vC[1]);
            MMA_F16(O[1], pa, vC[2], vC[3]);
            LDM_X4_T(vC, vb + 64);
            MMA_F16(O[2], pa, vN[0], vN[1]);
            MMA_F16(O[3], pa, vN[2], vN[3]);
            LDM_X4_T(vN, vb + 96);
            MMA_F16(O[4], pa, vC[0], vC[1]);
            MMA_F16(O[5], pa, vC[2], vC[3]);
            LDM_X4_T(vC, vb + 128);
            MMA_F16(O[6], pa, vN[0], vN[1]);
            MMA_F16(O[7], pa, vN[2], vN[3]);
            LDM_X4_T(vN, vb + 160);
            MMA_F16(O[8], pa, vC[0], vC[1]);
            MMA_F16(O[9], pa, vC[2], vC[3]);
            LDM_X4_T(vC, vb + 192);
            MMA_F16(O[10], pa, vN[0], vN[1]);
            MMA_F16(O[11], pa, vN[2], vN[3]);
            LDM_X4_T(vN, vb + 224);
            MMA_F16(O[12], pa, vC[0], vC[1]);
            MMA_F16(O[13], pa, vC[2], vC[3]);
            MMA_F16(O[14], pa, vN[0], vN[1]);
            MMA_F16(O[15], pa, vN[2], vN[3]);
        }
    }

    l0 += __shfl_xor_sync(0xffffffffu, l0, 1);
    l0 += __shfl_xor_sync(0xffffffffu, l0, 2);
    l1 += __shfl_xor_sync(0xffffffffu, l1, 1);
    l1 += __shfl_xor_sync(0xffffffffu, l1, 2);
    float inv0 = 1.f / l0;
    float inv1 = 1.f / l1;

#pragma unroll
    for (int nt = 0; nt < 16; nt++) {
        int colb = h * HDIM + nt * 8 + (lane & 3) * 2;
        *(half2*)(oh + (size_t)r0g * DMODEL + colb) =
            __floats2half2_rn(O[nt][0] * inv0, O[nt][1] * inv0);
        *(half2*)(oh + (size_t)r1g * DMODEL + colb) =
            __floats2half2_rn(O[nt][2] * inv1, O[nt][3] * inv1);
    }
}

// ---------------------------------------------------------------------------
// Launch
// ---------------------------------------------------------------------------
extern "C" void kernel_launch(void* const* d_in, const int* in_sizes, int n_in,
                              void* d_out, int out_size) {
    const float* x  = (const float*)d_in[0];
    const float* Wq = (const float*)d_in[1];
    const float* Wk = (const float*)d_in[2];
    const float* Wv = (const float*)d_in[3];
    const float* Wo = (const float*)d_in[4];
    float* out = (float*)d_out;

    __half *xh, *ah, *qhp, *khp, *vhp;
    __half *wq, *wk, *wv, *wo;
    float2* ropetab;
    cudaGetSymbolAddress((void**)&xh, g_xh);
    cudaGetSymbolAddress((void**)&ah, g_ah);
    cudaGetSymbolAddress((void**)&qhp, g_qh);
    cudaGetSymbolAddress((void**)&khp, g_kh);
    cudaGetSymbolAddress((void**)&vhp, g_vh);
    cudaGetSymbolAddress((void**)&wq, g_wq);
    cudaGetSymbolAddress((void**)&wk, g_wk);
    cudaGetSymbolAddress((void**)&wv, g_wv);
    cudaGetSymbolAddress((void**)&wo, g_wo);
    cudaGetSymbolAddress((void**)&ropetab, g_rope);

    cudaFuncSetAttribute(gemm_qkv,
                         cudaFuncAttributeMaxDynamicSharedMemorySize, GEMM_SMEM);
    cudaFuncSetAttribute(gemm_out,
                         cudaFuncAttributeMaxDynamicSharedMemorySize, GEMM_SMEM);
    cudaFuncSetAttribute(attn_mma,
                         cudaFuncAttributeMaxDynamicSharedMemorySize, ATTN_SMEM);

    const int nx8 = S_LEN * DMODEL / 8;
    const int nw8 = DMODEL * DMODEL / 8;
    rope_build<<<(S_LEN * 64 + 255) / 256, 256>>>(ropetab);
    cvt_f16<<<(nx8 + 255) / 256, 256>>>(x, xh, nx8);
    cvt_f16x4<<<dim3((nw8 + 255) / 256, 4), 256>>>(Wq, Wk, Wv, Wo,
                                                   wq, wk, wv, wo, nw8);

    dim3 gqkv(DMODEL / 128, S_LEN / 128, 3);
    gemm_qkv<<<gqkv, 512, GEMM_SMEM>>>(xh, wq, wk, wv, qhp, khp, vhp, ropetab);

    attn_mma<<<dim3(S_LEN / 128, NHEADS), 256, ATTN_SMEM>>>(qhp, khp, vhp, ah);

    dim3 go(DMODEL / 128, S_LEN / 128);
    gemm_out<<<go, 512, GEMM_SMEM>>>(ah, wo, out);
}